// round 16
// baseline (speedup 1.0000x reference)
#include <cuda_runtime.h>
#include <cuda_bf16.h>
#include <math_constants.h>
#include <cstdint>

#define BB 32
#define CC 9
#define TT 4096
#define NC 512
#define CD 64
#define MBLK 256          // positions per block
#define KP_B 112          // SMEM row stride bytes (3x32B segments + 16 pad)
#define NROWS (BB * CC)   // 288 real rows
#define NPAIR (NROWS / 2) // 144 packed FFTs

#define OFF_IDX ((size_t)BB * TT * CD)
#define OFF_PH  (OFF_IDX + (size_t)BB * TT)

// SMEM map for quant kernel (bytes)
#define SM_A    0u        // 256 * 112 = 28672
#define SM_B    28672u    // 512 * 112 = 57344
#define SM_CN   86016u    // 2048
#define SM_IDX  88064u    // 1024
#define SMEMSZ  89088     // 2 CTAs/SM

#define FFT_SMEM (4 * TT * 4)   // float2 s[4096] + float2 tw[4096] = 64 KB

// ---------------- global scratch ----------------
__device__ float g_im[BB * CC * TT];                  // Hilbert imag (unnormalized)
__device__ __align__(16) __nv_bfloat16 g_B[NC * 48];  // per code: hi|hi|lo segs of 16
__device__ float g_cn[NC];                            // ||c||^2 - 2*b.c

__device__ __forceinline__ uint32_t smem_to_u32(const void* p) {
    uint32_t a;
    asm("{ .reg .u64 t; cvta.to.shared.u64 t, %1; cvt.u32.u64 %0, t; }"
        : "=r"(a) : "l"(p));
    return a;
}

#define LDSM_X4(r0, r1, r2, r3, addr) \
    asm volatile("ldmatrix.sync.aligned.m8n8.x4.shared.b16 {%0,%1,%2,%3}, [%4];" \
                 : "=r"(r0), "=r"(r1), "=r"(r2), "=r"(r3) : "r"(addr))

#define MMA16816(d, a, b0, b1) \
    asm volatile("mma.sync.aligned.m16n8k16.row.col.f32.bf16.bf16.f32 " \
                 "{%0,%1,%2,%3}, {%4,%5,%6,%7}, {%8,%9}, {%0,%1,%2,%3};" \
                 : "+f"((d)[0]), "+f"((d)[1]), "+f"((d)[2]), "+f"((d)[3]) \
                 : "r"((a)[0]), "r"((a)[1]), "r"((a)[2]), "r"((a)[3]), \
                   "r"(b0), "r"(b1))

#define CP_ASYNC16(saddr, gptr) \
    asm volatile("cp.async.cg.shared.global [%0], [%1], 16;" \
                 :: "r"(saddr), "l"(gptr) : "memory")
#define CP_COMMIT() asm volatile("cp.async.commit_group;" ::: "memory")
#define CP_WAIT(n)  asm volatile("cp.async.wait_group %0;" :: "n"(n) : "memory")

__device__ __forceinline__ float2 cmulf(float2 a, float2 b) {
    return make_float2(a.x * b.x - a.y * b.y, a.x * b.y + a.y * b.x);
}
__device__ __forceinline__ float2 f2add(float2 a, float2 b) {
    return make_float2(a.x + b.x, a.y + b.y);
}
__device__ __forceinline__ float2 f2sub(float2 a, float2 b) {
    return make_float2(a.x - b.x, a.y - b.y);
}

__device__ __forceinline__ void split_pack(float v0, float v1,
                                           uint32_t& hp, uint32_t& lp) {
    __nv_bfloat16 h0 = __float2bfloat16(v0), h1 = __float2bfloat16(v1);
    __nv_bfloat16 l0 = __float2bfloat16(v0 - __bfloat162float(h0));
    __nv_bfloat16 l1 = __float2bfloat16(v1 - __bfloat162float(h1));
    hp = ((uint32_t)__bfloat16_as_ushort(h1) << 16) | __bfloat16_as_ushort(h0);
    lp = ((uint32_t)__bfloat16_as_ushort(l1) << 16) | __bfloat16_as_ushort(l0);
}

// ---------------- kernel 1: packed Hilbert FFT (1024 thr) + codebook proj ----
// blocks [0, NPAIR): two real rows packed as one complex FFT.
// blocks [NPAIR, NPAIR+16): per-code projection (warp per code, 32 warps).
__global__ void __launch_bounds__(1024, 1)
fft_conv_kernel(const float* __restrict__ imu,
                const float* __restrict__ cb,
                const float* __restrict__ Wm,
                const float* __restrict__ bm,
                const float* __restrict__ Wp,
                const float* __restrict__ bp) {
    const int tid = threadIdx.x;

    if (blockIdx.x >= NPAIR) {
        // ---- codebook projection: warp per code (32 warps per block) ----
        const int wid = tid >> 5, lane = tid & 31;
        const int c = (blockIdx.x - NPAIR) * 32 + wid;
        const float cl = cb[(size_t)c * CD + lane];
        const float chn = cb[(size_t)c * CD + 32 + lane];

        float red[20];
#pragma unroll
        for (int j = 0; j < 9; ++j) {
            red[j]     = Wm[lane * 9 + j] * cl;
            red[9 + j] = Wp[lane * 9 + j] * chn;
        }
        red[18] = bm[lane] * cl + bp[lane] * chn;
        red[19] = cl * cl + chn * chn;
#pragma unroll
        for (int off = 16; off >= 1; off >>= 1)
#pragma unroll
            for (int v = 0; v < 20; ++v)
                red[v] += __shfl_xor_sync(0xffffffffu, red[v], off);

        if (lane == 0) {
            float e[12];
#pragma unroll
            for (int j = 0; j < 7; ++j) e[j] = red[j] + red[9 + j];
            e[7] = red[7];  e[8] = red[8];
            e[9] = red[16]; e[10] = red[17];
            e[11] = 0.0f;
            uint32_t hi[6], lo[6];
#pragma unroll
            for (int q = 0; q < 6; ++q)
                split_pack(e[2 * q], e[2 * q + 1], hi[q], lo[q]);
            uint32_t* row32 = (uint32_t*)(g_B + (size_t)c * 48);
#pragma unroll
            for (int q = 0; q < 6; ++q) {
                row32[q] = hi[q];           // seg0: c_hi
                row32[8 + q] = hi[q];       // seg1: c_hi
                row32[16 + q] = lo[q];      // seg2: c_lo
            }
            row32[6] = 0u; row32[7] = 0u;
            row32[14] = 0u; row32[15] = 0u;
            row32[22] = 0u; row32[23] = 0u;
            g_cn[c] = red[19] - 2.0f * red[18];
        }
        return;
    }

    extern __shared__ float2 dsh[];
    float2* s = dsh;            // 4096
    float2* tw = dsh + TT;      // 4096: tw[k] = exp(-2*pi*i*k/4096)
    const float* x0 = imu + (size_t)(2 * blockIdx.x) * TT;
    const float* x1 = x0 + TT;

    // quarter twiddle table: 1 sincosf + 3 exact rotations per thread
    {
        const int k = tid;   // 0..1023
        float sn, cs;
        sincosf(-(float)CUDART_PI_F * (float)k / 2048.0f, &sn, &cs);
        tw[k] = make_float2(cs, sn);
        tw[k + 1024] = make_float2(sn, -cs);
        tw[k + 2048] = make_float2(-cs, -sn);
        tw[k + 3072] = make_float2(-sn, cs);
    }
    for (int t = tid; t < TT; t += 1024)
        s[t] = make_float2(x0[t], x1[t]);
    __syncthreads();

    // Forward radix-4 DIF: natural in, base-4 digit-reversed out.
#pragma unroll
    for (int ls = 10; ls >= 0; ls -= 2) {
        const int L = 1 << ls;
        const int m = 1024 >> ls;
        {
            const int i = tid;   // 1024 butterflies, 1 per thread
            const int j = i & (L - 1);
            const int i0 = ((i >> ls) << (ls + 2)) + j;
            float2 a = s[i0], b = s[i0 + L], c = s[i0 + 2 * L], d = s[i0 + 3 * L];
            float2 t0 = f2add(a, c), t1 = f2sub(a, c);
            float2 t2 = f2add(b, d), t3 = f2sub(b, d);
            s[i0] = f2add(t0, t2);
            s[i0 + L] = cmulf(make_float2(t1.x + t3.y, t1.y - t3.x), tw[j * m]);
            s[i0 + 2 * L] = cmulf(f2sub(t0, t2), tw[2 * j * m]);
            s[i0 + 3 * L] = cmulf(make_float2(t1.x - t3.y, t1.y + t3.x), tw[3 * j * m]);
        }
        __syncthreads();
    }

    // Hilbert multiplier M[k] = -i*sgn(k) at base-4 digit-reversed slot.
    for (int p = tid; p < TT; p += 1024) {
        const int r = (int)(__brev((unsigned)p) >> 20);
        const int k = ((r & 0x555) << 1) | ((r >> 1) & 0x555);
        float2 v = s[p];
        if (k == 0 || k == TT / 2)  s[p] = make_float2(0.0f, 0.0f);
        else if (k < TT / 2)        s[p] = make_float2(v.y, -v.x);
        else                        s[p] = make_float2(-v.y, v.x);
    }
    __syncthreads();

    // Inverse radix-4 DIT: digit-reversed in, natural out (conj twiddles, no 1/N).
#pragma unroll
    for (int ls = 0; ls <= 10; ls += 2) {
        const int L = 1 << ls;
        const int m = 1024 >> ls;
        {
            const int i = tid;
            const int j = i & (L - 1);
            const int i0 = ((i >> ls) << (ls + 2)) + j;
            float2 w1 = tw[j * m], w2 = tw[2 * j * m], w3 = tw[3 * j * m];
            float2 A = s[i0];
            float2 Bv = cmulf(s[i0 + L],     make_float2(w1.x, -w1.y));
            float2 Cv = cmulf(s[i0 + 2 * L], make_float2(w2.x, -w2.y));
            float2 Dv = cmulf(s[i0 + 3 * L], make_float2(w3.x, -w3.y));
            float2 t0 = f2add(A, Cv), t1 = f2sub(A, Cv);
            float2 t2 = f2add(Bv, Dv), t3 = f2sub(Bv, Dv);
            s[i0] = f2add(t0, t2);
            s[i0 + L] = make_float2(t1.x - t3.y, t1.y + t3.x);
            s[i0 + 2 * L] = f2sub(t0, t2);
            s[i0 + 3 * L] = make_float2(t1.x + t3.y, t1.y - t3.x);
        }
        __syncthreads();
    }

    // write raw Hilbert imag (atan2 deferred to quant kernel)
    float* w0 = g_im + (size_t)(2 * blockIdx.x) * TT;
    float* w1 = w0 + TT;
    for (int t = tid; t < TT; t += 1024) {
        const float2 v = s[t];
        w0[t] = v.x;
        w1[t] = v.y;
    }
}

// ---------------- kernel 2: phases + u-projection + K=48 HMMA + argmin ----
// 512 threads, 16 m-warps (m16 each), whole B resident, barrier-free loop.
__global__ void __launch_bounds__(512, 2)
quant_kernel(const float* __restrict__ imu,
             const float* __restrict__ cb,
             float* __restrict__ out) {
    extern __shared__ char smem[];
    const uint32_t sbase = smem_to_u32(smem);
    const int tid = threadIdx.x;
    const int wid = tid >> 5;
    const int lane = tid & 31;
    const int pbase = blockIdx.x * MBLK;

    float* scn = (float*)(smem + SM_CN);
    int* sidx = (int*)(smem + SM_IDX);

    // prefetch the WHOLE projected codebook: 512 rows x 96 B = 3072 uint4
    {
        const char* src = (const char*)g_B;
#pragma unroll
        for (int it = 0; it < 6; ++it) {
            const int i = tid + it * 512;
            const int r = i / 6, q = i - r * 6;
            CP_ASYNC16(sbase + SM_B + (uint32_t)r * KP_B + (uint32_t)q * 16u,
                       src + (size_t)r * 96 + (size_t)q * 16);
        }
        CP_COMMIT();
    }

    for (int i = tid; i < NC; i += 512) scn[i] = g_cn[i];

    // ---- per-channel atan2 + mean + u-vector for 256 positions -> SMEM A
    if (tid < MBLK) {
        const int p = pbase + tid;
        const int b = p >> 12;
        const int t = p & (TT - 1);

        const float* xb = imu + (size_t)b * CC * TT + t;
        const float* imb = g_im + (size_t)b * CC * TT + t;
        float u[12];
        float pm = 0.0f;
#pragma unroll
        for (int c = 0; c < 9; ++c) {
            u[c] = xb[c * TT];
            pm += atan2f(imb[c * TT], 4096.0f * u[c]);
        }
        pm *= (1.0f / 9.0f);
        float sp, cp;
        sincosf(pm, &sp, &cp);
        out[OFF_PH + p] = pm;
        u[9] = cp;
        u[10] = sp;
        u[11] = 0.0f;

        uint32_t* row32 = (uint32_t*)(smem + SM_A + (uint32_t)tid * KP_B);
#pragma unroll
        for (int q = 0; q < 6; ++q) {
            uint32_t hp, lp;
            split_pack(u[2 * q], u[2 * q + 1], hp, lp);
            row32[q] = hp;            // seg0: u_hi
            row32[8 + q] = lp;        // seg1: u_lo
            row32[16 + q] = hp;       // seg2: u_hi
        }
        row32[6] = 0u; row32[7] = 0u;
        row32[14] = 0u; row32[15] = 0u;
        row32[22] = 0u; row32[23] = 0u;
    }
    CP_WAIT(0);
    __syncthreads();   // A + B + cn all visible; no more barriers until epilogue

    // ---- GEMM + argmin. Warp w: rows 16w..16w+15, all 512 codes.
    const int m0 = wid * 16;

    const int mgrp = lane >> 3;     // 0..3
    const int mrow = lane & 7;
    const uint32_t a_base = sbase + SM_A
        + (uint32_t)(m0 + mrow + 8 * (mgrp & 1)) * KP_B
        + (uint32_t)(8 * (mgrp >> 1)) * 2u;
    const uint32_t b_row_off = (uint32_t)(8 * (mgrp >> 1) + mrow) * KP_B
        + (uint32_t)(8 * (mgrp & 1)) * 2u;

    // ---- A fragments register-resident: [kstep][4] = 12 regs
    uint32_t afr[3][4];
#pragma unroll
    for (int k = 0; k < 3; ++k)
        LDSM_X4(afr[k][0], afr[k][1], afr[k][2], afr[k][3],
                a_base + (uint32_t)k * 32u);

    float best[2];
    int bidx[2];
    best[0] = CUDART_INF_F; best[1] = CUDART_INF_F;
    bidx[0] = 0; bidx[1] = 0;

#pragma unroll 1
    for (int ch = 0; ch < 16; ++ch) {
        const uint32_t sBc = sbase + SM_B + (uint32_t)ch * (32 * KP_B);

        float acc[4][4];
#pragma unroll
        for (int j = 0; j < 4; ++j)
#pragma unroll
            for (int q = 0; q < 4; ++q) acc[j][q] = 0.0f;

#pragma unroll
        for (int g = 0; g < 2; ++g) {
            const uint32_t bb = sBc + (uint32_t)(g * 16) * KP_B + b_row_off;
            uint32_t bq[3][4];
#pragma unroll
            for (int k = 0; k < 3; ++k)
                LDSM_X4(bq[k][0], bq[k][1], bq[k][2], bq[k][3],
                        bb + (uint32_t)k * 32u);
#pragma unroll
            for (int k = 0; k < 3; ++k) {
                MMA16816(acc[2 * g],     afr[k], bq[k][0], bq[k][1]);
                MMA16816(acc[2 * g + 1], afr[k], bq[k][2], bq[k][3]);
            }
        }

        // running argmin (codes strictly increasing -> first-min kept)
#pragma unroll
        for (int j = 0; j < 4; ++j) {
            const int c0 = ch * 32 + (j >> 1) * 16 + (j & 1) * 8 + (lane & 3) * 2;
            const float n0v = scn[c0], n1v = scn[c0 + 1];
            const float d0 = fmaf(-2.0f, acc[j][0], n0v);
            const float d1 = fmaf(-2.0f, acc[j][1], n1v);
            const float d2 = fmaf(-2.0f, acc[j][2], n0v);
            const float d3 = fmaf(-2.0f, acc[j][3], n1v);
            if (d0 < best[0]) { best[0] = d0; bidx[0] = c0; }
            if (d1 < best[0]) { best[0] = d1; bidx[0] = c0 + 1; }
            if (d2 < best[1]) { best[1] = d2; bidx[1] = c0; }
            if (d3 < best[1]) { best[1] = d3; bidx[1] = c0 + 1; }
        }
    }

    // reduce across the 4 lanes sharing each row (quad)
#pragma unroll
    for (int off = 1; off <= 2; off <<= 1) {
#pragma unroll
        for (int s = 0; s < 2; ++s) {
            float ob = __shfl_xor_sync(0xffffffffu, best[s], off);
            int oi = __shfl_xor_sync(0xffffffffu, bidx[s], off);
            if (ob < best[s] || (ob == best[s] && oi < bidx[s])) {
                best[s] = ob; bidx[s] = oi;
            }
        }
    }
    if ((lane & 3) == 0) {
        const int r = lane >> 2;
        const int row_lo = m0 + r;
        const int row_hi = m0 + 8 + r;
        sidx[row_lo] = bidx[0];
        sidx[row_hi] = bidx[1];
        out[OFF_IDX + pbase + row_lo] = (float)bidx[0];
        out[OFF_IDX + pbase + row_hi] = (float)bidx[1];
    }
    __syncthreads();

    // quantized rows from fp32 codebook (L2-hot)
    const float4* cb4 = (const float4*)cb;
    for (int q = tid; q < MBLK * (CD / 4); q += 512) {
        const int pos = q >> 4;
        const int w = q & 15;
        ((float4*)(out + (size_t)(pbase + pos) * CD))[w] =
            cb4[(size_t)sidx[pos] * (CD / 4) + w];
    }
}

// ---------------- launch ----------------
extern "C" void kernel_launch(void* const* d_in, const int* in_sizes, int n_in,
                              void* d_out, int out_size) {
    const float* imu = (const float*)d_in[0];
    const float* Wm  = (const float*)d_in[1];
    const float* bm  = (const float*)d_in[2];
    const float* Wp  = (const float*)d_in[3];
    const float* bp  = (const float*)d_in[4];
    const float* cb  = (const float*)d_in[5];
    float* out = (float*)d_out;

    cudaFuncSetAttribute(fft_conv_kernel,
                         cudaFuncAttributeMaxDynamicSharedMemorySize, FFT_SMEM);
    fft_conv_kernel<<<NPAIR + NC / 32, 1024, FFT_SMEM>>>(imu, cb, Wm, bm, Wp, bp);

    cudaFuncSetAttribute(quant_kernel,
                         cudaFuncAttributeMaxDynamicSharedMemorySize, SMEMSZ);
    quant_kernel<<<(BB * TT) / MBLK, 512, SMEMSZ>>>(imu, cb, out);
}

// round 17
// speedup vs baseline: 1.0552x; 1.0552x over previous
#include <cuda_runtime.h>
#include <cuda_bf16.h>
#include <math_constants.h>
#include <cstdint>

#define BB 32
#define CC 9
#define TT 4096
#define NC 512
#define CD 64
#define MBLK 256          // positions per block
#define KP_B 112          // SMEM row stride bytes (3x32B segments + 16 pad)
#define NROWS (BB * CC)   // 288 real rows
#define NPAIR (NROWS / 2) // 144 packed FFTs

#define OFF_IDX ((size_t)BB * TT * CD)
#define OFF_PH  (OFF_IDX + (size_t)BB * TT)

// SMEM map for quant kernel (bytes)
#define SM_A    0u        // 256 * 112 = 28672
#define SM_B    28672u    // 512 * 112 = 57344
#define SM_CN   86016u    // 2048
#define SM_IDX  88064u    // 1024
#define SMEMSZ  89088     // 2 CTAs/SM

#define FFT_SMEM (4 * TT * 4)   // float2 s[4096] + float2 tw[4096] = 64 KB

// ---------------- global scratch ----------------
__device__ float g_phase[BB * CC * TT];
__device__ __align__(16) __nv_bfloat16 g_B[NC * 48];  // per code: hi|hi|lo segs of 16
__device__ float g_cn[NC];                            // ||c||^2 - 2*b.c

__device__ __forceinline__ uint32_t smem_to_u32(const void* p) {
    uint32_t a;
    asm("{ .reg .u64 t; cvta.to.shared.u64 t, %1; cvt.u32.u64 %0, t; }"
        : "=r"(a) : "l"(p));
    return a;
}

#define LDSM_X4(r0, r1, r2, r3, addr) \
    asm volatile("ldmatrix.sync.aligned.m8n8.x4.shared.b16 {%0,%1,%2,%3}, [%4];" \
                 : "=r"(r0), "=r"(r1), "=r"(r2), "=r"(r3) : "r"(addr))

#define MMA16816(d, a, b0, b1) \
    asm volatile("mma.sync.aligned.m16n8k16.row.col.f32.bf16.bf16.f32 " \
                 "{%0,%1,%2,%3}, {%4,%5,%6,%7}, {%8,%9}, {%0,%1,%2,%3};" \
                 : "+f"((d)[0]), "+f"((d)[1]), "+f"((d)[2]), "+f"((d)[3]) \
                 : "r"((a)[0]), "r"((a)[1]), "r"((a)[2]), "r"((a)[3]), \
                   "r"(b0), "r"(b1))

#define CP_ASYNC16(saddr, gptr) \
    asm volatile("cp.async.cg.shared.global [%0], [%1], 16;" \
                 :: "r"(saddr), "l"(gptr) : "memory")
#define CP_COMMIT() asm volatile("cp.async.commit_group;" ::: "memory")
#define CP_WAIT(n)  asm volatile("cp.async.wait_group %0;" :: "n"(n) : "memory")

__device__ __forceinline__ float2 cmulf(float2 a, float2 b) {
    return make_float2(a.x * b.x - a.y * b.y, a.x * b.y + a.y * b.x);
}
__device__ __forceinline__ float2 f2add(float2 a, float2 b) {
    return make_float2(a.x + b.x, a.y + b.y);
}
__device__ __forceinline__ float2 f2sub(float2 a, float2 b) {
    return make_float2(a.x - b.x, a.y - b.y);
}

__device__ __forceinline__ void split_pack(float v0, float v1,
                                           uint32_t& hp, uint32_t& lp) {
    __nv_bfloat16 h0 = __float2bfloat16(v0), h1 = __float2bfloat16(v1);
    __nv_bfloat16 l0 = __float2bfloat16(v0 - __bfloat162float(h0));
    __nv_bfloat16 l1 = __float2bfloat16(v1 - __bfloat162float(h1));
    hp = ((uint32_t)__bfloat16_as_ushort(h1) << 16) | __bfloat16_as_ushort(h0);
    lp = ((uint32_t)__bfloat16_as_ushort(l1) << 16) | __bfloat16_as_ushort(l0);
}

// ---------------- kernel 1: packed Hilbert FFT (1024 thr) + codebook proj ----
// blocks [0, NPAIR): two real rows packed as one complex FFT; atan2 in tail.
// blocks [NPAIR, NPAIR+16): per-code projection (warp per code, 32 warps).
__global__ void __launch_bounds__(1024, 1)
fft_conv_kernel(const float* __restrict__ imu,
                const float* __restrict__ cb,
                const float* __restrict__ Wm,
                const float* __restrict__ bm,
                const float* __restrict__ Wp,
                const float* __restrict__ bp) {
    const int tid = threadIdx.x;

    if (blockIdx.x >= NPAIR) {
        // ---- codebook projection: warp per code (32 warps per block) ----
        const int wid = tid >> 5, lane = tid & 31;
        const int c = (blockIdx.x - NPAIR) * 32 + wid;
        const float cl = cb[(size_t)c * CD + lane];
        const float chn = cb[(size_t)c * CD + 32 + lane];

        float red[20];
#pragma unroll
        for (int j = 0; j < 9; ++j) {
            red[j]     = Wm[lane * 9 + j] * cl;
            red[9 + j] = Wp[lane * 9 + j] * chn;
        }
        red[18] = bm[lane] * cl + bp[lane] * chn;
        red[19] = cl * cl + chn * chn;
#pragma unroll
        for (int off = 16; off >= 1; off >>= 1)
#pragma unroll
            for (int v = 0; v < 20; ++v)
                red[v] += __shfl_xor_sync(0xffffffffu, red[v], off);

        if (lane == 0) {
            float e[12];
#pragma unroll
            for (int j = 0; j < 7; ++j) e[j] = red[j] + red[9 + j];
            e[7] = red[7];  e[8] = red[8];
            e[9] = red[16]; e[10] = red[17];
            e[11] = 0.0f;
            uint32_t hi[6], lo[6];
#pragma unroll
            for (int q = 0; q < 6; ++q)
                split_pack(e[2 * q], e[2 * q + 1], hi[q], lo[q]);
            uint32_t* row32 = (uint32_t*)(g_B + (size_t)c * 48);
#pragma unroll
            for (int q = 0; q < 6; ++q) {
                row32[q] = hi[q];           // seg0: c_hi
                row32[8 + q] = hi[q];       // seg1: c_hi
                row32[16 + q] = lo[q];      // seg2: c_lo
            }
            row32[6] = 0u; row32[7] = 0u;
            row32[14] = 0u; row32[15] = 0u;
            row32[22] = 0u; row32[23] = 0u;
            g_cn[c] = red[19] - 2.0f * red[18];
        }
        return;
    }

    extern __shared__ float2 dsh[];
    float2* s = dsh;            // 4096
    float2* tw = dsh + TT;      // 4096: tw[k] = exp(-2*pi*i*k/4096)
    const float* x0 = imu + (size_t)(2 * blockIdx.x) * TT;
    const float* x1 = x0 + TT;

    // quarter twiddle table: 1 sincosf + 3 exact rotations per thread
    {
        const int k = tid;   // 0..1023
        float sn, cs;
        sincosf(-(float)CUDART_PI_F * (float)k / 2048.0f, &sn, &cs);
        tw[k] = make_float2(cs, sn);
        tw[k + 1024] = make_float2(sn, -cs);
        tw[k + 2048] = make_float2(-cs, -sn);
        tw[k + 3072] = make_float2(-sn, cs);
    }
    for (int t = tid; t < TT; t += 1024)
        s[t] = make_float2(x0[t], x1[t]);
    __syncthreads();

    // Forward radix-4 DIF: natural in, base-4 digit-reversed out.
#pragma unroll
    for (int ls = 10; ls >= 0; ls -= 2) {
        const int L = 1 << ls;
        const int m = 1024 >> ls;
        {
            const int i = tid;   // 1024 butterflies, 1 per thread
            const int j = i & (L - 1);
            const int i0 = ((i >> ls) << (ls + 2)) + j;
            float2 a = s[i0], b = s[i0 + L], c = s[i0 + 2 * L], d = s[i0 + 3 * L];
            float2 t0 = f2add(a, c), t1 = f2sub(a, c);
            float2 t2 = f2add(b, d), t3 = f2sub(b, d);
            s[i0] = f2add(t0, t2);
            s[i0 + L] = cmulf(make_float2(t1.x + t3.y, t1.y - t3.x), tw[j * m]);
            s[i0 + 2 * L] = cmulf(f2sub(t0, t2), tw[2 * j * m]);
            s[i0 + 3 * L] = cmulf(make_float2(t1.x - t3.y, t1.y + t3.x), tw[3 * j * m]);
        }
        __syncthreads();
    }

    // Hilbert multiplier M[k] = -i*sgn(k) at base-4 digit-reversed slot.
    for (int p = tid; p < TT; p += 1024) {
        const int r = (int)(__brev((unsigned)p) >> 20);
        const int k = ((r & 0x555) << 1) | ((r >> 1) & 0x555);
        float2 v = s[p];
        if (k == 0 || k == TT / 2)  s[p] = make_float2(0.0f, 0.0f);
        else if (k < TT / 2)        s[p] = make_float2(v.y, -v.x);
        else                        s[p] = make_float2(-v.y, v.x);
    }
    __syncthreads();

    // Inverse radix-4 DIT: digit-reversed in, natural out (conj twiddles, no 1/N).
#pragma unroll
    for (int ls = 0; ls <= 10; ls += 2) {
        const int L = 1 << ls;
        const int m = 1024 >> ls;
        {
            const int i = tid;
            const int j = i & (L - 1);
            const int i0 = ((i >> ls) << (ls + 2)) + j;
            float2 w1 = tw[j * m], w2 = tw[2 * j * m], w3 = tw[3 * j * m];
            float2 A = s[i0];
            float2 Bv = cmulf(s[i0 + L],     make_float2(w1.x, -w1.y));
            float2 Cv = cmulf(s[i0 + 2 * L], make_float2(w2.x, -w2.y));
            float2 Dv = cmulf(s[i0 + 3 * L], make_float2(w3.x, -w3.y));
            float2 t0 = f2add(A, Cv), t1 = f2sub(A, Cv);
            float2 t2 = f2add(Bv, Dv), t3 = f2sub(Bv, Dv);
            s[i0] = f2add(t0, t2);
            s[i0 + L] = make_float2(t1.x - t3.y, t1.y + t3.x);
            s[i0 + 2 * L] = f2sub(t0, t2);
            s[i0 + 3 * L] = make_float2(t1.x + t3.y, t1.y - t3.x);
        }
        __syncthreads();
    }

    // phases: Re(analytic) = x exactly; Im unnormalized -> scale x by N instead
    float* ph0 = g_phase + (size_t)(2 * blockIdx.x) * TT;
    float* ph1 = ph0 + TT;
    for (int t = tid; t < TT; t += 1024) {
        const float2 v = s[t];
        ph0[t] = atan2f(v.x, 4096.0f * x0[t]);
        ph1[t] = atan2f(v.y, 4096.0f * x1[t]);
    }
}

// ---------------- kernel 2: u-projection + K=48 HMMA GEMM + argmin ----------
// 512 threads, 16 m-warps (m16 each), whole B resident, barrier-free loop.
__global__ void __launch_bounds__(512, 2)
quant_kernel(const float* __restrict__ imu,
             const float* __restrict__ cb,
             float* __restrict__ out) {
    extern __shared__ char smem[];
    const uint32_t sbase = smem_to_u32(smem);
    const int tid = threadIdx.x;
    const int wid = tid >> 5;
    const int lane = tid & 31;
    const int pbase = blockIdx.x * MBLK;

    float* scn = (float*)(smem + SM_CN);
    int* sidx = (int*)(smem + SM_IDX);

    // prefetch the WHOLE projected codebook: 512 rows x 96 B = 3072 uint4
    {
        const char* src = (const char*)g_B;
#pragma unroll
        for (int it = 0; it < 6; ++it) {
            const int i = tid + it * 512;
            const int r = i / 6, q = i - r * 6;
            CP_ASYNC16(sbase + SM_B + (uint32_t)r * KP_B + (uint32_t)q * 16u,
                       src + (size_t)r * 96 + (size_t)q * 16);
        }
        CP_COMMIT();
    }

    for (int i = tid; i < NC; i += 512) scn[i] = g_cn[i];

    // ---- u-vector for 256 positions -> SMEM A (bf16 hi|lo|hi segments)
    if (tid < MBLK) {
        const int p = pbase + tid;
        const int b = p >> 12;
        const int t = p & (TT - 1);

        const float* xb = imu + (size_t)b * CC * TT + t;
        float u[12];
#pragma unroll
        for (int c = 0; c < 9; ++c) u[c] = xb[c * TT];

        const float* phb = g_phase + (size_t)b * CC * TT + t;
        float pm = 0.0f;
#pragma unroll
        for (int c = 0; c < 9; ++c) pm += phb[c * TT];
        pm *= (1.0f / 9.0f);
        float sp, cp;
        sincosf(pm, &sp, &cp);
        out[OFF_PH + p] = pm;
        u[9] = cp;
        u[10] = sp;
        u[11] = 0.0f;

        uint32_t* row32 = (uint32_t*)(smem + SM_A + (uint32_t)tid * KP_B);
#pragma unroll
        for (int q = 0; q < 6; ++q) {
            uint32_t hp, lp;
            split_pack(u[2 * q], u[2 * q + 1], hp, lp);
            row32[q] = hp;            // seg0: u_hi
            row32[8 + q] = lp;        // seg1: u_lo
            row32[16 + q] = hp;       // seg2: u_hi
        }
        row32[6] = 0u; row32[7] = 0u;
        row32[14] = 0u; row32[15] = 0u;
        row32[22] = 0u; row32[23] = 0u;
    }
    CP_WAIT(0);
    __syncthreads();   // A + B + cn all visible; no more barriers until epilogue

    // ---- GEMM + argmin. Warp w: rows 16w..16w+15, all 512 codes.
    const int m0 = wid * 16;

    const int mgrp = lane >> 3;     // 0..3
    const int mrow = lane & 7;
    const uint32_t a_base = sbase + SM_A
        + (uint32_t)(m0 + mrow + 8 * (mgrp & 1)) * KP_B
        + (uint32_t)(8 * (mgrp >> 1)) * 2u;
    const uint32_t b_row_off = (uint32_t)(8 * (mgrp >> 1) + mrow) * KP_B
        + (uint32_t)(8 * (mgrp & 1)) * 2u;

    // ---- A fragments register-resident: [kstep][4] = 12 regs
    uint32_t afr[3][4];
#pragma unroll
    for (int k = 0; k < 3; ++k)
        LDSM_X4(afr[k][0], afr[k][1], afr[k][2], afr[k][3],
                a_base + (uint32_t)k * 32u);

    float best[2];
    int bidx[2];
    best[0] = CUDART_INF_F; best[1] = CUDART_INF_F;
    bidx[0] = 0; bidx[1] = 0;

#pragma unroll 1
    for (int ch = 0; ch < 16; ++ch) {
        const uint32_t sBc = sbase + SM_B + (uint32_t)ch * (32 * KP_B);

        float acc[4][4];
#pragma unroll
        for (int j = 0; j < 4; ++j)
#pragma unroll
            for (int q = 0; q < 4; ++q) acc[j][q] = 0.0f;

#pragma unroll
        for (int g = 0; g < 2; ++g) {
            const uint32_t bb = sBc + (uint32_t)(g * 16) * KP_B + b_row_off;
            uint32_t bq[3][4];
#pragma unroll
            for (int k = 0; k < 3; ++k)
                LDSM_X4(bq[k][0], bq[k][1], bq[k][2], bq[k][3],
                        bb + (uint32_t)k * 32u);
#pragma unroll
            for (int k = 0; k < 3; ++k) {
                MMA16816(acc[2 * g],     afr[k], bq[k][0], bq[k][1]);
                MMA16816(acc[2 * g + 1], afr[k], bq[k][2], bq[k][3]);
            }
        }

        // running argmin (codes strictly increasing -> first-min kept)
#pragma unroll
        for (int j = 0; j < 4; ++j) {
            const int c0 = ch * 32 + (j >> 1) * 16 + (j & 1) * 8 + (lane & 3) * 2;
            const float n0v = scn[c0], n1v = scn[c0 + 1];
            const float d0 = fmaf(-2.0f, acc[j][0], n0v);
            const float d1 = fmaf(-2.0f, acc[j][1], n1v);
            const float d2 = fmaf(-2.0f, acc[j][2], n0v);
            const float d3 = fmaf(-2.0f, acc[j][3], n1v);
            if (d0 < best[0]) { best[0] = d0; bidx[0] = c0; }
            if (d1 < best[0]) { best[0] = d1; bidx[0] = c0 + 1; }
            if (d2 < best[1]) { best[1] = d2; bidx[1] = c0; }
            if (d3 < best[1]) { best[1] = d3; bidx[1] = c0 + 1; }
        }
    }

    // reduce across the 4 lanes sharing each row (quad)
#pragma unroll
    for (int off = 1; off <= 2; off <<= 1) {
#pragma unroll
        for (int s = 0; s < 2; ++s) {
            float ob = __shfl_xor_sync(0xffffffffu, best[s], off);
            int oi = __shfl_xor_sync(0xffffffffu, bidx[s], off);
            if (ob < best[s] || (ob == best[s] && oi < bidx[s])) {
                best[s] = ob; bidx[s] = oi;
            }
        }
    }
    if ((lane & 3) == 0) {
        const int r = lane >> 2;
        const int row_lo = m0 + r;
        const int row_hi = m0 + 8 + r;
        sidx[row_lo] = bidx[0];
        sidx[row_hi] = bidx[1];
        out[OFF_IDX + pbase + row_lo] = (float)bidx[0];
        out[OFF_IDX + pbase + row_hi] = (float)bidx[1];
    }
    __syncthreads();

    // quantized rows from fp32 codebook (L2-hot)
    const float4* cb4 = (const float4*)cb;
    for (int q = tid; q < MBLK * (CD / 4); q += 512) {
        const int pos = q >> 4;
        const int w = q & 15;
        ((float4*)(out + (size_t)(pbase + pos) * CD))[w] =
            cb4[(size_t)sidx[pos] * (CD / 4) + w];
    }
}

// ---------------- launch ----------------
extern "C" void kernel_launch(void* const* d_in, const int* in_sizes, int n_in,
                              void* d_out, int out_size) {
    const float* imu = (const float*)d_in[0];
    const float* Wm  = (const float*)d_in[1];
    const float* bm  = (const float*)d_in[2];
    const float* Wp  = (const float*)d_in[3];
    const float* bp  = (const float*)d_in[4];
    const float* cb  = (const float*)d_in[5];
    float* out = (float*)d_out;

    cudaFuncSetAttribute(fft_conv_kernel,
                         cudaFuncAttributeMaxDynamicSharedMemorySize, FFT_SMEM);
    fft_conv_kernel<<<NPAIR + NC / 32, 1024, FFT_SMEM>>>(imu, cb, Wm, bm, Wp, bp);

    cudaFuncSetAttribute(quant_kernel,
                         cudaFuncAttributeMaxDynamicSharedMemorySize, SMEMSZ);
    quant_kernel<<<(BB * TT) / MBLK, 512, SMEMSZ>>>(imu, cb, out);
}